// round 6
// baseline (speedup 1.0000x reference)
#include <cuda_runtime.h>
#include <math.h>
#include <stdint.h>

#define Bz     4
#define Tt     2048
#define Dm     1024
#define Hh     16
#define Dh     64
#define Mrows  (Bz * Tt)     // 8192

__device__ float g_Q[Mrows * Dm];
__device__ float g_K[Mrows * Dm];
__device__ float g_V[Mrows * Dm];
__device__ float g_ctx[Mrows * Dm];

__device__ __forceinline__ uint32_t f2tf32(float x) {
    uint32_t r;
    asm("cvt.rna.tf32.f32 %0, %1;" : "=r"(r) : "f"(x));
    return r;
}

// ============ tf32 GEMM with fragment-permuted smem, reg-prefetch pipeline ============
// C[M,N]=A[M,K]*B[K,N]; block 128x128, BK=32, 8 warps (4 m x 2 n), warp tile 32x64.
// Aperm: [tm(8)][k8(4)][lane(32)][4]  word w = slot (half*2+rowhalf)
// Bperm: [tp(8)][k8(4)][lane(32)][4]  word w = (tn&1)*2 + half
#define BM 128
#define BN 128
#define BK 32
#define TILEW 4096                       // words per A (or B) stage
#define GEMM_SMEM_BYTES (4 * TILEW * 4)  // 2 bufs x (A+B)
#define KITERS (Dm / BK)                 // 32

__device__ __forceinline__ void gemm_tf32_body(const float* __restrict__ A,
                                               const float* __restrict__ B,
                                               float* __restrict__ C)
{
    extern __shared__ uint32_t gsm[];
    uint32_t* As = gsm;              // [2][TILEW]
    uint32_t* Bs = gsm + 2 * TILEW;  // [2][TILEW]

    const int tid  = threadIdx.x;
    const int lane = tid & 31;
    const int warp = tid >> 5;
    const int wm   = warp >> 1;
    const int wn   = warp & 1;
    const int bM = blockIdx.y * BM;
    const int bN = blockIdx.x * BN;

    const float* Ablk = A + (size_t)bM * Dm;
    const float* Bblk = B + bN;

    float4 ra[4], rb[4];

    float acc[2][8][4];
    #pragma unroll
    for (int mt = 0; mt < 2; mt++)
        #pragma unroll
        for (int nt = 0; nt < 8; nt++)
            #pragma unroll
            for (int i = 0; i < 4; i++) acc[mt][nt][i] = 0.f;

    auto ldg_tile = [&](int k0) {
        #pragma unroll
        for (int i = 0; i < 4; i++) {
            int f = tid + i * 256;
            int row = f >> 3, c4 = (f & 7) * 4;
            ra[i] = *(const float4*)(Ablk + (size_t)row * Dm + k0 + c4);
            int krow = f >> 5, c4b = (f & 31) * 4;
            rb[i] = *(const float4*)(Bblk + (size_t)(k0 + krow) * Dm + c4b);
        }
    };

    auto sts_tile = [&](int buf) {
        uint32_t* Ad = As + buf * TILEW;
        uint32_t* Bd = Bs + buf * TILEW;
        #pragma unroll
        for (int i = 0; i < 4; i++) {
            int f = tid + i * 256;
            {   // A element (row, col=c4+w)
                int row = f >> 3, c4 = (f & 7) * 4;
                int tm = row >> 4, rr = row & 15, rh = rr >> 3, arr = rr & 7;
                float v[4] = {ra[i].x, ra[i].y, ra[i].z, ra[i].w};
                #pragma unroll
                for (int w = 0; w < 4; w++) {
                    int col = c4 + w, k8 = col >> 3, acc_ = col & 7;
                    int half = acc_ >> 2, ac_ = acc_ & 3;
                    Ad[(((tm * 4 + k8) * 32 + 4 * arr + ac_) << 2) + half * 2 + rh] = f2tf32(v[w]);
                }
            }
            {   // B element (krow, col=c4+w)
                int krow = f >> 5, c4 = (f & 31) * 4;
                int k8 = krow >> 3, acd = krow & 7, half = acd >> 2, ack = acd & 3;
                float v[4] = {rb[i].x, rb[i].y, rb[i].z, rb[i].w};
                #pragma unroll
                for (int w = 0; w < 4; w++) {
                    int col = c4 + w, tn = col >> 3, arn = col & 7;
                    int tp = tn >> 1, par = tn & 1;
                    Bd[(((tp * 4 + k8) * 32 + 4 * arn + ack) << 2) + par * 2 + half] = f2tf32(v[w]);
                }
            }
        }
    };

    ldg_tile(0);
    for (int it = 0; it < KITERS; it++) {
        const int buf = it & 1;
        sts_tile(buf);
        __syncthreads();
        if (it + 1 < KITERS) ldg_tile((it + 1) * BK);

        const uint32_t* Ab = As + buf * TILEW;
        const uint32_t* Bb = Bs + buf * TILEW;
        #pragma unroll
        for (int k8 = 0; k8 < 4; k8++) {
            uint4 af[2];
            #pragma unroll
            for (int mt = 0; mt < 2; mt++) {
                const int tm = wm * 2 + mt;
                af[mt] = *(const uint4*)&Ab[((tm * 4 + k8) * 32 + lane) << 2];
            }
            #pragma unroll
            for (int tpi = 0; tpi < 4; tpi++) {
                const int tp = wn * 4 + tpi;
                uint4 bf = *(const uint4*)&Bb[((tp * 4 + k8) * 32 + lane) << 2];
                #pragma unroll
                for (int mt = 0; mt < 2; mt++) {
                    asm volatile(
                        "mma.sync.aligned.m16n8k8.row.col.f32.tf32.tf32.f32 "
                        "{%0,%1,%2,%3}, {%4,%5,%6,%7}, {%8,%9}, {%0,%1,%2,%3};\n"
                        : "+f"(acc[mt][2*tpi][0]), "+f"(acc[mt][2*tpi][1]),
                          "+f"(acc[mt][2*tpi][2]), "+f"(acc[mt][2*tpi][3])
                        : "r"(af[mt].x), "r"(af[mt].y), "r"(af[mt].z), "r"(af[mt].w),
                          "r"(bf.x), "r"(bf.y));
                    asm volatile(
                        "mma.sync.aligned.m16n8k8.row.col.f32.tf32.tf32.f32 "
                        "{%0,%1,%2,%3}, {%4,%5,%6,%7}, {%8,%9}, {%0,%1,%2,%3};\n"
                        : "+f"(acc[mt][2*tpi+1][0]), "+f"(acc[mt][2*tpi+1][1]),
                          "+f"(acc[mt][2*tpi+1][2]), "+f"(acc[mt][2*tpi+1][3])
                        : "r"(af[mt].x), "r"(af[mt].y), "r"(af[mt].z), "r"(af[mt].w),
                          "r"(bf.z), "r"(bf.w));
                }
            }
        }
        __syncthreads();
    }

    const int ar = lane >> 2;
    const int ac = lane & 3;
    #pragma unroll
    for (int mt = 0; mt < 2; mt++) {
        const int row0 = bM + wm * 32 + mt * 16 + ar;
        #pragma unroll
        for (int nt = 0; nt < 8; nt++) {
            const int col = bN + wn * 64 + nt * 8 + ac * 2;
            *(float2*)(C + (size_t)row0 * Dm + col)       = make_float2(acc[mt][nt][0], acc[mt][nt][1]);
            *(float2*)(C + (size_t)(row0 + 8) * Dm + col) = make_float2(acc[mt][nt][2], acc[mt][nt][3]);
        }
    }
}

__global__ __launch_bounds__(256, 2) void gemm_qkv(const float* __restrict__ x,
                                                   const float* __restrict__ Wq,
                                                   const float* __restrict__ Wk,
                                                   const float* __restrict__ Wv)
{
    const float* W = (blockIdx.z == 0) ? Wq : (blockIdx.z == 1) ? Wk : Wv;
    float*       C = (blockIdx.z == 0) ? g_Q : (blockIdx.z == 1) ? g_K : g_V;
    gemm_tf32_body(x, W, C);
}

__global__ __launch_bounds__(256, 2) void gemm_out(const float* __restrict__ Wo,
                                                   float* __restrict__ out)
{
    gemm_tf32_body(g_ctx, Wo, out);
}

// ======================= tensor-core causal flash attention =======================
// 256 threads (8 warps); warp w owns 16 query rows. 128 q rows/CTA, key tiles of 64.
// Qperm [tm(8)][k8(8)][lane][4]; Kperm/Vperm [tp(4)][k8(8)][lane][4]; P row-major.
#define PS 68
#define QPW  8192
#define KPW  4096
#define VPW  4096
#define ATTN_SMEM_WORDS (QPW + KPW + VPW + 128 * PS)
#define ATTN_SMEM_BYTES (ATTN_SMEM_WORDS * 4)

__global__ __launch_bounds__(256, 2) void attn_mma()
{
    extern __shared__ uint32_t smw[];
    uint32_t* Qp  = smw;             // 8192
    uint32_t* Kp  = Qp + QPW;        // 4096
    uint32_t* Vp  = Kp + KPW;        // 4096
    uint32_t* Psm = Vp + VPW;        // 8 warps x 16 x PS

    const int tid  = threadIdx.x;
    const int lane = tid & 31;
    const int warp = tid >> 5;
    const int ar   = lane >> 2;
    const int ac   = lane & 3;

    const int qt = blockIdx.x, h = blockIdx.y, b = blockIdx.z;
    const int q0 = qt * 128;

    // ---- stage Q tile into A-perm layout (scale folded) ----
    const float* Qg = g_Q + ((size_t)(b * Tt + q0)) * Dm + h * Dh;
    #pragma unroll
    for (int i = 0; i < 8; i++) {
        int f = tid + i * 256;
        int row = f >> 4, c4 = (f & 15) * 4;
        float4 v = *(const float4*)(Qg + (size_t)row * Dm + c4);
        float vv[4] = {v.x, v.y, v.z, v.w};
        int tm = row >> 4, rr = row & 15, rh = rr >> 3, arr = rr & 7;
        #pragma unroll
        for (int w = 0; w < 4; w++) {
            int col = c4 + w, k8 = col >> 3, acc_ = col & 7;
            int half = acc_ >> 2, ac_ = acc_ & 3;
            Qp[(((tm * 8 + k8) * 32 + 4 * arr + ac_) << 2) + half * 2 + rh] =
                f2tf32(vv[w] * 0.125f);
        }
    }

    float accO[8][4];
    #pragma unroll
    for (int nt = 0; nt < 8; nt++)
        #pragma unroll
        for (int i = 0; i < 4; i++) accO[nt][i] = 0.f;

    float mrow0 = -1e30f, mrow1 = -1e30f, lrow0 = 0.f, lrow1 = 0.f;

    uint32_t* Pw = Psm + warp * 16 * PS;
    const int ntiles = 2 * qt + 2;

    for (int kt = 0; kt < ntiles; kt++) {
        const size_t kvbase = ((size_t)(b * Tt + kt * 64)) * Dm + h * Dh;
        __syncthreads();
        #pragma unroll
        for (int i = 0; i < 4; i++) {
            int f = tid + i * 256;
            int row = f >> 4, c4 = (f & 15) * 4;   // row = key index, c4 = d base
            {   // K as B-matrix: n=key, k=d
                float4 kv = *(const float4*)(g_K + kvbase + (size_t)row * Dm + c4);
                float vv[4] = {kv.x, kv.y, kv.z, kv.w};
                int tn = row >> 3, gid = row & 7, tp = tn >> 1, par = tn & 1;
                #pragma unroll
                for (int w = 0; w < 4; w++) {
                    int d = c4 + w, k8 = d >> 3, acd = d & 7;
                    int half = acd >> 2, ack = acd & 3;
                    Kp[(((tp * 8 + k8) * 32 + 4 * gid + ack) << 2) + par * 2 + half] = f2tf32(vv[w]);
                }
            }
            {   // V as B-matrix: n=d, k=key
                float4 vv4 = *(const float4*)(g_V + kvbase + (size_t)row * Dm + c4);
                float vv[4] = {vv4.x, vv4.y, vv4.z, vv4.w};
                int k8 = row >> 3, acd = row & 7, half = acd >> 2, ack = acd & 3;
                #pragma unroll
                for (int w = 0; w < 4; w++) {
                    int d = c4 + w, tn = d >> 3, gid = d & 7;
                    int tp = tn >> 1, par = tn & 1;
                    Vp[(((tp * 8 + k8) * 32 + 4 * gid + ack) << 2) + par * 2 + half] = f2tf32(vv[w]);
                }
            }
        }
        __syncthreads();

        // ---- S = Q K^T (warp: 16 x 64) ----
        float s[8][4];
        #pragma unroll
        for (int nt = 0; nt < 8; nt++)
            #pragma unroll
            for (int i = 0; i < 4; i++) s[nt][i] = 0.f;

        #pragma unroll
        for (int k8 = 0; k8 < 8; k8++) {
            uint4 qa = *(const uint4*)&Qp[((warp * 8 + k8) * 32 + lane) << 2];
            #pragma unroll
            for (int tpi = 0; tpi < 4; tpi++) {
                uint4 kb = *(const uint4*)&Kp[((tpi * 8 + k8) * 32 + lane) << 2];
                asm volatile(
                    "mma.sync.aligned.m16n8k8.row.col.f32.tf32.tf32.f32 "
                    "{%0,%1,%2,%3}, {%4,%5,%6,%7}, {%8,%9}, {%0,%1,%2,%3};\n"
                    : "+f"(s[2*tpi][0]), "+f"(s[2*tpi][1]), "+f"(s[2*tpi][2]), "+f"(s[2*tpi][3])
                    : "r"(qa.x), "r"(qa.y), "r"(qa.z), "r"(qa.w), "r"(kb.x), "r"(kb.y));
                asm volatile(
                    "mma.sync.aligned.m16n8k8.row.col.f32.tf32.tf32.f32 "
                    "{%0,%1,%2,%3}, {%4,%5,%6,%7}, {%8,%9}, {%0,%1,%2,%3};\n"
                    : "+f"(s[2*tpi+1][0]), "+f"(s[2*tpi+1][1]), "+f"(s[2*tpi+1][2]), "+f"(s[2*tpi+1][3])
                    : "r"(qa.x), "r"(qa.y), "r"(qa.z), "r"(qa.w), "r"(kb.z), "r"(kb.w));
            }
        }

        // ---- mask (edge tiles) + online softmax ----
        const int r0 = q0 + warp * 16 + ar;
        if (kt >= 2 * qt) {
            #pragma unroll
            for (int nt = 0; nt < 8; nt++) {
                const int c0 = kt * 64 + nt * 8 + 2 * ac;
                if (c0     > r0    ) s[nt][0] = -1e30f;
                if (c0 + 1 > r0    ) s[nt][1] = -1e30f;
                if (c0     > r0 + 8) s[nt][2] = -1e30f;
                if (c0 + 1 > r0 + 8) s[nt][3] = -1e30f;
            }
        }
        float mx0 = -1e30f, mx1 = -1e30f;
        #pragma unroll
        for (int nt = 0; nt < 8; nt++) {
            mx0 = fmaxf(mx0, fmaxf(s[nt][0], s[nt][1]));
            mx1 = fmaxf(mx1, fmaxf(s[nt][2], s[nt][3]));
        }
        mx0 = fmaxf(mx0, __shfl_xor_sync(0xffffffff, mx0, 1));
        mx0 = fmaxf(mx0, __shfl_xor_sync(0xffffffff, mx0, 2));
        mx1 = fmaxf(mx1, __shfl_xor_sync(0xffffffff, mx1, 1));
        mx1 = fmaxf(mx1, __shfl_xor_sync(0xffffffff, mx1, 2));

        const float mn0 = fmaxf(mrow0, mx0);
        const float mn1 = fmaxf(mrow1, mx1);
        const float corr0 = __expf(mrow0 - mn0);
        const float corr1 = __expf(mrow1 - mn1);
        mrow0 = mn0; mrow1 = mn1;

        float ls0 = 0.f, ls1 = 0.f;
        #pragma unroll
        for (int nt = 0; nt < 8; nt++) {
            float p00 = __expf(s[nt][0] - mn0);
            float p01 = __expf(s[nt][1] - mn0);
            float p10 = __expf(s[nt][2] - mn1);
            float p11 = __expf(s[nt][3] - mn1);
            ls0 += p00 + p01;
            ls1 += p10 + p11;
            uint32_t* pw = Pw + ar * PS + nt * 8 + 2 * ac;
            pw[0]          = f2tf32(p00);
            pw[1]          = f2tf32(p01);
            pw[8 * PS]     = f2tf32(p10);
            pw[8 * PS + 1] = f2tf32(p11);
        }
        ls0 += __shfl_xor_sync(0xffffffff, ls0, 1);
        ls0 += __shfl_xor_sync(0xffffffff, ls0, 2);
        ls1 += __shfl_xor_sync(0xffffffff, ls1, 1);
        ls1 += __shfl_xor_sync(0xffffffff, ls1, 2);
        lrow0 = lrow0 * corr0 + ls0;
        lrow1 = lrow1 * corr1 + ls1;

        #pragma unroll
        for (int nt = 0; nt < 8; nt++) {
            accO[nt][0] *= corr0; accO[nt][1] *= corr0;
            accO[nt][2] *= corr1; accO[nt][3] *= corr1;
        }
        __syncwarp();

        // ---- O += P V (warp: 16 x 64, K=64 keys) ----
        #pragma unroll
        for (int k8 = 0; k8 < 8; k8++) {
            const int k = k8 * 8;
            uint32_t a0 = Pw[(ar    ) * PS + k + ac];
            uint32_t a1 = Pw[(ar + 8) * PS + k + ac];
            uint32_t a2 = Pw[(ar    ) * PS + k + ac + 4];
            uint32_t a3 = Pw[(ar + 8) * PS + k + ac + 4];
            #pragma unroll
            for (int tpi = 0; tpi < 4; tpi++) {
                uint4 vb = *(const uint4*)&Vp[((tpi * 8 + k8) * 32 + lane) << 2];
                asm volatile(
                    "mma.sync.aligned.m16n8k8.row.col.f32.tf32.tf32.f32 "
                    "{%0,%1,%2,%3}, {%4,%5,%6,%7}, {%8,%9}, {%0,%1,%2,%3};\n"
                    : "+f"(accO[2*tpi][0]), "+f"(accO[2*tpi][1]),
                      "+f"(accO[2*tpi][2]), "+f"(accO[2*tpi][3])
                    : "r"(a0), "r"(a1), "r"(a2), "r"(a3), "r"(vb.x), "r"(vb.y));
                asm volatile(
                    "mma.sync.aligned.m16n8k8.row.col.f32.tf32.tf32.f32 "
                    "{%0,%1,%2,%3}, {%4,%5,%6,%7}, {%8,%9}, {%0,%1,%2,%3};\n"
                    : "+f"(accO[2*tpi+1][0]), "+f"(accO[2*tpi+1][1]),
                      "+f"(accO[2*tpi+1][2]), "+f"(accO[2*tpi+1][3])
                    : "r"(a0), "r"(a1), "r"(a2), "r"(a3), "r"(vb.z), "r"(vb.w));
            }
        }
    }

    // ---- normalize + store ----
    const float inv0 = 1.f / lrow0;
    const float inv1 = 1.f / lrow1;
    const int r0 = q0 + warp * 16 + ar;
    float* og = g_ctx + ((size_t)(b * Tt)) * Dm + h * Dh;
    #pragma unroll
    for (int nt = 0; nt < 8; nt++) {
        const int col = nt * 8 + 2 * ac;
        *(float2*)(og + (size_t)r0 * Dm + col) =
            make_float2(accO[nt][0] * inv0, accO[nt][1] * inv0);
        *(float2*)(og + (size_t)(r0 + 8) * Dm + col) =
            make_float2(accO[nt][2] * inv1, accO[nt][3] * inv1);
    }
}

// ======================= launch =======================
extern "C" void kernel_launch(void* const* d_in, const int* in_sizes, int n_in,
                              void* d_out, int out_size)
{
    const float* x  = (const float*)d_in[0];
    const float* Wq = (const float*)d_in[1];
    const float* Wk = (const float*)d_in[2];
    const float* Wv = (const float*)d_in[3];
    const float* Wo = (const float*)d_in[4];
    float* out = (float*)d_out;

    static int attr_done = 0;
    if (!attr_done) {
        cudaFuncSetAttribute(gemm_qkv, cudaFuncAttributeMaxDynamicSharedMemorySize, GEMM_SMEM_BYTES);
        cudaFuncSetAttribute(gemm_out, cudaFuncAttributeMaxDynamicSharedMemorySize, GEMM_SMEM_BYTES);
        cudaFuncSetAttribute(attn_mma, cudaFuncAttributeMaxDynamicSharedMemorySize, ATTN_SMEM_BYTES);
        attr_done = 1;
    }

    dim3 gQKV(Dm / BN, Mrows / BM, 3);
    gemm_qkv<<<gQKV, 256, GEMM_SMEM_BYTES>>>(x, Wq, Wk, Wv);

    dim3 gA(Tt / 128, Hh, Bz);
    attn_mma<<<gA, 256, ATTN_SMEM_BYTES>>>();

    dim3 gO(Dm / BN, Mrows / BM, 1);
    gemm_out<<<gO, 256, GEMM_SMEM_BYTES>>>(Wo, out);
}

// round 7
// speedup vs baseline: 1.9927x; 1.9927x over previous
#include <cuda_runtime.h>
#include <math.h>
#include <stdint.h>

#define Bz     4
#define Tt     2048
#define Dm     1024
#define Hh     16
#define Dh     64
#define Mrows  (Bz * Tt)     // 8192

__device__ float g_Q[Mrows * Dm];
__device__ float g_K[Mrows * Dm];
__device__ float g_V[Mrows * Dm];
__device__ float g_ctx[Mrows * Dm];

__device__ __forceinline__ uint32_t f2tf32(float x) {
    uint32_t r;
    asm("cvt.rna.tf32.f32 %0, %1;" : "=r"(r) : "f"(x));
    return r;
}

__device__ __forceinline__ void cp16(void* dst_smem, const void* src) {
    uint32_t d = (uint32_t)__cvta_generic_to_shared(dst_smem);
    asm volatile("cp.async.cg.shared.global [%0], [%1], 16;\n" :: "r"(d), "l"(src));
}
#define CP_COMMIT() asm volatile("cp.async.commit_group;\n" ::: "memory")
#define CP_WAIT1()  asm volatile("cp.async.wait_group 1;\n" ::: "memory")

// ========== tf32 GEMM: 128x128x32 CTA tile, 4 warps @ 64x64, cp.async 2-stage ==========
#define BM 128
#define BN 128
#define BK 32
#define AS_STRIDE 36    // banks (4r+c) distinct -> conflict-free A frag loads
#define BS_STRIDE 136   // banks (8k+n) distinct -> conflict-free B frag loads
#define ASTGW (BM * AS_STRIDE)
#define BSTGW (BK * BS_STRIDE)
#define GEMM_SMEM_BYTES ((2 * (ASTGW + BSTGW)) * 4)
#define KITERS (Dm / BK)   // 32

__device__ __forceinline__ void gemm_tf32_body(const float* __restrict__ A,
                                               const float* __restrict__ B,
                                               float* __restrict__ C)
{
    extern __shared__ float gsm[];
    float* As = gsm;                // [2][ASTGW] raw fp32
    float* Bs = gsm + 2 * ASTGW;    // [2][BSTGW]

    const int tid  = threadIdx.x;   // 0..127
    const int lane = tid & 31;
    const int warp = tid >> 5;      // 0..3
    const int wm   = warp >> 1;     // 0..1
    const int wn   = warp & 1;      // 0..1
    const int bM = blockIdx.y * BM;
    const int bN = blockIdx.x * BN;
    const int ar = lane >> 2;
    const int ac = lane & 3;

    const float* Ablk = A + (size_t)bM * Dm;
    const float* Bblk = B + bN;

    float acc[4][8][4];
    #pragma unroll
    for (int mt = 0; mt < 4; mt++)
        #pragma unroll
        for (int nt = 0; nt < 8; nt++)
            #pragma unroll
            for (int i = 0; i < 4; i++) acc[mt][nt][i] = 0.f;

    auto stage = [&](int k0, int buf) {
        float* Ad = As + buf * ASTGW;
        float* Bd = Bs + buf * BSTGW;
        #pragma unroll
        for (int i = 0; i < 8; i++) {
            int f   = tid + i * 128;
            int row = f >> 3;                 // A: 8 float4 per row
            int c4  = (f & 7) * 4;
            cp16(Ad + row * AS_STRIDE + c4, Ablk + (size_t)row * Dm + k0 + c4);
        }
        #pragma unroll
        for (int i = 0; i < 8; i++) {
            int f    = tid + i * 128;
            int krow = f >> 5;                // B: 32 float4 per row
            int c4   = (f & 31) * 4;
            cp16(Bd + krow * BS_STRIDE + c4, Bblk + (size_t)(k0 + krow) * Dm + c4);
        }
    };

    stage(0, 0);
    CP_COMMIT();

    for (int it = 0; it < KITERS; it++) {
        const int buf = it & 1;
        if (it + 1 < KITERS) stage((it + 1) * BK, buf ^ 1);
        CP_COMMIT();
        CP_WAIT1();
        __syncthreads();

        const float* Ab = As + buf * ASTGW;
        const float* Bb = Bs + buf * BSTGW;
        #pragma unroll
        for (int k8 = 0; k8 < BK / 8; k8++) {
            const int k = k8 * 8;
            uint32_t af[4][4];
            #pragma unroll
            for (int mt = 0; mt < 4; mt++) {
                const int mo = wm * 64 + mt * 16;
                af[mt][0] = f2tf32(Ab[(mo + ar    ) * AS_STRIDE + k + ac]);
                af[mt][1] = f2tf32(Ab[(mo + ar + 8) * AS_STRIDE + k + ac]);
                af[mt][2] = f2tf32(Ab[(mo + ar    ) * AS_STRIDE + k + ac + 4]);
                af[mt][3] = f2tf32(Ab[(mo + ar + 8) * AS_STRIDE + k + ac + 4]);
            }
            #pragma unroll
            for (int nt = 0; nt < 8; nt++) {
                const int no = wn * 64 + nt * 8;
                uint32_t b0 = f2tf32(Bb[(k + ac    ) * BS_STRIDE + no + ar]);
                uint32_t b1 = f2tf32(Bb[(k + ac + 4) * BS_STRIDE + no + ar]);
                #pragma unroll
                for (int mt = 0; mt < 4; mt++) {
                    asm volatile(
                        "mma.sync.aligned.m16n8k8.row.col.f32.tf32.tf32.f32 "
                        "{%0,%1,%2,%3}, {%4,%5,%6,%7}, {%8,%9}, {%0,%1,%2,%3};\n"
                        : "+f"(acc[mt][nt][0]), "+f"(acc[mt][nt][1]),
                          "+f"(acc[mt][nt][2]), "+f"(acc[mt][nt][3])
                        : "r"(af[mt][0]), "r"(af[mt][1]),
                          "r"(af[mt][2]), "r"(af[mt][3]),
                          "r"(b0), "r"(b1));
                }
            }
        }
        __syncthreads();
    }

    #pragma unroll
    for (int mt = 0; mt < 4; mt++) {
        const int row0 = bM + wm * 64 + mt * 16 + ar;
        #pragma unroll
        for (int nt = 0; nt < 8; nt++) {
            const int col = bN + wn * 64 + nt * 8 + ac * 2;
            *(float2*)(C + (size_t)row0 * Dm + col)       = make_float2(acc[mt][nt][0], acc[mt][nt][1]);
            *(float2*)(C + (size_t)(row0 + 8) * Dm + col) = make_float2(acc[mt][nt][2], acc[mt][nt][3]);
        }
    }
}

__global__ __launch_bounds__(128, 2) void gemm_qkv(const float* __restrict__ x,
                                                   const float* __restrict__ Wq,
                                                   const float* __restrict__ Wk,
                                                   const float* __restrict__ Wv)
{
    const float* W = (blockIdx.z == 0) ? Wq : (blockIdx.z == 1) ? Wk : Wv;
    float*       C = (blockIdx.z == 0) ? g_Q : (blockIdx.z == 1) ? g_K : g_V;
    gemm_tf32_body(x, W, C);
}

__global__ __launch_bounds__(128, 2) void gemm_out(const float* __restrict__ Wo,
                                                   float* __restrict__ out)
{
    gemm_tf32_body(g_ctx, Wo, out);
}

// ======================= tensor-core causal flash attention (R4 version) =======================
// 256 threads (8 warps); warp w owns 16 query rows. 128 q rows/CTA, key tiles of 64.
#define QS 68
#define KS 68
#define VS 72
#define PS 68
#define ATTN_SMEM_WORDS (128*QS + 64*KS + 64*VS + 128*PS)
#define ATTN_SMEM_BYTES (ATTN_SMEM_WORDS * 4)

__global__ __launch_bounds__(256, 2) void attn_mma()
{
    extern __shared__ uint32_t smw[];
    uint32_t* Qs  = smw;
    uint32_t* Ksm = Qs  + 128 * QS;
    uint32_t* Vsm = Ksm + 64 * KS;
    uint32_t* Psm = Vsm + 64 * VS;

    const int tid  = threadIdx.x;
    const int lane = tid & 31;
    const int warp = tid >> 5;
    const int ar   = lane >> 2;
    const int ac   = lane & 3;

    const int qt = blockIdx.x, h = blockIdx.y, b = blockIdx.z;
    const int q0 = qt * 128;

    const float* Qg = g_Q + ((size_t)(b * Tt + q0)) * Dm + h * Dh;
    #pragma unroll
    for (int i = 0; i < 8; i++) {
        int f = tid + i * 256;
        int row = f >> 4;
        int c4  = (f & 15) * 4;
        float4 v = *(const float4*)(Qg + (size_t)row * Dm + c4);
        uint32_t* d = &Qs[row * QS + c4];
        d[0] = f2tf32(v.x * 0.125f); d[1] = f2tf32(v.y * 0.125f);
        d[2] = f2tf32(v.z * 0.125f); d[3] = f2tf32(v.w * 0.125f);
    }

    float accO[8][4];
    #pragma unroll
    for (int nt = 0; nt < 8; nt++)
        #pragma unroll
        for (int i = 0; i < 4; i++) accO[nt][i] = 0.f;

    float mrow0 = -1e30f, mrow1 = -1e30f, lrow0 = 0.f, lrow1 = 0.f;

    uint32_t* Pw = Psm + warp * 16 * PS;
    const int ntiles = 2 * qt + 2;

    for (int kt = 0; kt < ntiles; kt++) {
        const size_t kvbase = ((size_t)(b * Tt + kt * 64)) * Dm + h * Dh;
        __syncthreads();
        #pragma unroll
        for (int i = 0; i < 4; i++) {
            int f = tid + i * 256;
            int row = f >> 4;
            int c4  = (f & 15) * 4;
            float4 kv = *(const float4*)(g_K + kvbase + (size_t)row * Dm + c4);
            uint32_t* dk = &Ksm[row * KS + c4];
            dk[0] = f2tf32(kv.x); dk[1] = f2tf32(kv.y);
            dk[2] = f2tf32(kv.z); dk[3] = f2tf32(kv.w);
            float4 vv = *(const float4*)(g_V + kvbase + (size_t)row * Dm + c4);
            uint32_t* dv = &Vsm[row * VS + c4];
            dv[0] = f2tf32(vv.x); dv[1] = f2tf32(vv.y);
            dv[2] = f2tf32(vv.z); dv[3] = f2tf32(vv.w);
        }
        __syncthreads();

        float s[8][4];
        #pragma unroll
        for (int nt = 0; nt < 8; nt++)
            #pragma unroll
            for (int i = 0; i < 4; i++) s[nt][i] = 0.f;

        #pragma unroll
        for (int k8 = 0; k8 < 8; k8++) {
            const int k = k8 * 8;
            const int mo = warp * 16;
            uint32_t a0 = Qs[(mo + ar    ) * QS + k + ac];
            uint32_t a1 = Qs[(mo + ar + 8) * QS + k + ac];
            uint32_t a2 = Qs[(mo + ar    ) * QS + k + ac + 4];
            uint32_t a3 = Qs[(mo + ar + 8) * QS + k + ac + 4];
            #pragma unroll
            for (int nt = 0; nt < 8; nt++) {
                const int n = nt * 8;
                uint32_t b0 = Ksm[(n + ar) * KS + k + ac];
                uint32_t b1 = Ksm[(n + ar) * KS + k + ac + 4];
                asm volatile(
                    "mma.sync.aligned.m16n8k8.row.col.f32.tf32.tf32.f32 "
                    "{%0,%1,%2,%3}, {%4,%5,%6,%7}, {%8,%9}, {%0,%1,%2,%3};\n"
                    : "+f"(s[nt][0]), "+f"(s[nt][1]), "+f"(s[nt][2]), "+f"(s[nt][3])
                    : "r"(a0), "r"(a1), "r"(a2), "r"(a3), "r"(b0), "r"(b1));
            }
        }

        const int r0 = q0 + warp * 16 + ar;
        if (kt >= 2 * qt) {
            #pragma unroll
            for (int nt = 0; nt < 8; nt++) {
                const int c0 = kt * 64 + nt * 8 + 2 * ac;
                if (c0     > r0    ) s[nt][0] = -1e30f;
                if (c0 + 1 > r0    ) s[nt][1] = -1e30f;
                if (c0     > r0 + 8) s[nt][2] = -1e30f;
                if (c0 + 1 > r0 + 8) s[nt][3] = -1e30f;
            }
        }
        float mx0 = -1e30f, mx1 = -1e30f;
        #pragma unroll
        for (int nt = 0; nt < 8; nt++) {
            mx0 = fmaxf(mx0, fmaxf(s[nt][0], s[nt][1]));
            mx1 = fmaxf(mx1, fmaxf(s[nt][2], s[nt][3]));
        }
        mx0 = fmaxf(mx0, __shfl_xor_sync(0xffffffff, mx0, 1));
        mx0 = fmaxf(mx0, __shfl_xor_sync(0xffffffff, mx0, 2));
        mx1 = fmaxf(mx1, __shfl_xor_sync(0xffffffff, mx1, 1));
        mx1 = fmaxf(mx1, __shfl_xor_sync(0xffffffff, mx1, 2));

        const float mn0 = fmaxf(mrow0, mx0);
        const float mn1 = fmaxf(mrow1, mx1);
        const float corr0 = __expf(mrow0 - mn0);
        const float corr1 = __expf(mrow1 - mn1);
        mrow0 = mn0; mrow1 = mn1;

        float ls0 = 0.f, ls1 = 0.f;
        #pragma unroll
        for (int nt = 0; nt < 8; nt++) {
            float p00 = __expf(s[nt][0] - mn0);
            float p01 = __expf(s[nt][1] - mn0);
            float p10 = __expf(s[nt][2] - mn1);
            float p11 = __expf(s[nt][3] - mn1);
            ls0 += p00 + p01;
            ls1 += p10 + p11;
            uint32_t* pw = Pw + ar * PS + nt * 8 + 2 * ac;
            pw[0]          = f2tf32(p00);
            pw[1]          = f2tf32(p01);
            pw[8 * PS]     = f2tf32(p10);
            pw[8 * PS + 1] = f2tf32(p11);
        }
        ls0 += __shfl_xor_sync(0xffffffff, ls0, 1);
        ls0 += __shfl_xor_sync(0xffffffff, ls0, 2);
        ls1 += __shfl_xor_sync(0xffffffff, ls1, 1);
        ls1 += __shfl_xor_sync(0xffffffff, ls1, 2);
        lrow0 = lrow0 * corr0 + ls0;
        lrow1 = lrow1 * corr1 + ls1;

        #pragma unroll
        for (int nt = 0; nt < 8; nt++) {
            accO[nt][0] *= corr0; accO[nt][1] *= corr0;
            accO[nt][2] *= corr1; accO[nt][3] *= corr1;
        }
        __syncwarp();

        #pragma unroll
        for (int k8 = 0; k8 < 8; k8++) {
            const int k = k8 * 8;
            uint32_t a0 = Pw[(ar    ) * PS + k + ac];
            uint32_t a1 = Pw[(ar + 8) * PS + k + ac];
            uint32_t a2 = Pw[(ar    ) * PS + k + ac + 4];
            uint32_t a3 = Pw[(ar + 8) * PS + k + ac + 4];
            #pragma unroll
            for (int nt = 0; nt < 8; nt++) {
                const int n = nt * 8;
                uint32_t b0 = Vsm[(k + ac    ) * VS + n + ar];
                uint32_t b1 = Vsm[(k + ac + 4) * VS + n + ar];
                asm volatile(
                    "mma.sync.aligned.m16n8k8.row.col.f32.tf32.tf32.f32 "
                    "{%0,%1,%2,%3}, {%4,%5,%6,%7}, {%8,%9}, {%0,%1,%2,%3};\n"
                    : "+f"(accO[nt][0]), "+f"(accO[nt][1]),
                      "+f"(accO[nt][2]), "+f"(accO[nt][3])
                    : "r"(a0), "r"(a1), "r"(a2), "r"(a3), "r"(b0), "r"(b1));
            }
        }
    }

    const float inv0 = 1.f / lrow0;
    const float inv1 = 1.f / lrow1;
    const int r0 = q0 + warp * 16 + ar;
    float* og = g_ctx + ((size_t)(b * Tt)) * Dm + h * Dh;
    #pragma unroll
    for (int nt = 0; nt < 8; nt++) {
        const int col = nt * 8 + 2 * ac;
        *(float2*)(og + (size_t)r0 * Dm + col) =
            make_float2(accO[nt][0] * inv0, accO[nt][1] * inv0);
        *(float2*)(og + (size_t)(r0 + 8) * Dm + col) =
            make_float2(accO[nt][2] * inv1, accO[nt][3] * inv1);
    }
}

// ======================= launch =======================
extern "C" void kernel_launch(void* const* d_in, const int* in_sizes, int n_in,
                              void* d_out, int out_size)
{
    const float* x  = (const float*)d_in[0];
    const float* Wq = (const float*)d_in[1];
    const float* Wk = (const float*)d_in[2];
    const float* Wv = (const float*)d_in[3];
    const float* Wo = (const float*)d_in[4];
    float* out = (float*)d_out;

    static int attr_done = 0;
    if (!attr_done) {
        cudaFuncSetAttribute(gemm_qkv, cudaFuncAttributeMaxDynamicSharedMemorySize, GEMM_SMEM_BYTES);
        cudaFuncSetAttribute(gemm_out, cudaFuncAttributeMaxDynamicSharedMemorySize, GEMM_SMEM_BYTES);
        cudaFuncSetAttribute(attn_mma, cudaFuncAttributeMaxDynamicSharedMemorySize, ATTN_SMEM_BYTES);
        attr_done = 1;
    }

    dim3 gQKV(Dm / BN, Mrows / BM, 3);
    gemm_qkv<<<gQKV, 128, GEMM_SMEM_BYTES>>>(x, Wq, Wk, Wv);

    dim3 gA(Tt / 128, Hh, Bz);
    attn_mma<<<gA, 256, ATTN_SMEM_BYTES>>>();

    dim3 gO(Dm / BN, Mrows / BM, 1);
    gemm_out<<<gO, 128, GEMM_SMEM_BYTES>>>(Wo, out);
}

// round 10
// speedup vs baseline: 2.0728x; 1.0402x over previous
#include <cuda_runtime.h>
#include <math.h>
#include <stdint.h>

#define Bz     4
#define Tt     2048
#define Dm     1024
#define Hh     16
#define Dh     64
#define Mrows  (Bz * Tt)     // 8192

// ---- scratch ----
__device__ float g_Q[Mrows * Dm];
__device__ float g_K[Mrows * Dm];
__device__ float g_V[Mrows * Dm];
__device__ float g_ctx[Mrows * Dm];      // tf32-rounded by attn epilogue
__device__ float g_Wr[4][Dm * Dm];       // tf32-rounded weights (original [K,N] layout)
__device__ float g_Xr[Mrows * Dm];       // tf32-rounded x

__device__ __forceinline__ uint32_t f2tf32(float x) {
    uint32_t r;
    asm("cvt.rna.tf32.f32 %0, %1;" : "=r"(r) : "f"(x));
    return r;
}
__device__ __forceinline__ float roundtf(float x) { return __uint_as_float(f2tf32(x)); }
__device__ __forceinline__ float ex2f(float x) {
    float r;
    asm("ex2.approx.ftz.f32 %0, %1;" : "=f"(r) : "f"(x));
    return r;
}

__device__ __forceinline__ void cp16(void* dst_smem, const void* src) {
    uint32_t d = (uint32_t)__cvta_generic_to_shared(dst_smem);
    asm volatile("cp.async.cg.shared.global [%0], [%1], 16;\n" :: "r"(d), "l"(src));
}
#define CP_COMMIT() asm volatile("cp.async.commit_group;\n" ::: "memory")
#define CP_WAIT1()  asm volatile("cp.async.wait_group 1;\n" ::: "memory")

// ======================= prep: tf32-round x and W in place =======================
__global__ __launch_bounds__(256) void round_w(const float* __restrict__ Wq,
                                               const float* __restrict__ Wk,
                                               const float* __restrict__ Wv,
                                               const float* __restrict__ Wo)
{
    const float* W = (blockIdx.z == 0) ? Wq : (blockIdx.z == 1) ? Wk :
                     (blockIdx.z == 2) ? Wv : Wo;
    float* D = g_Wr[blockIdx.z];
    size_t i = ((size_t)blockIdx.x * 256 + threadIdx.x) * 4;
    float4 v = *(const float4*)(W + i);
    v.x = roundtf(v.x); v.y = roundtf(v.y); v.z = roundtf(v.z); v.w = roundtf(v.w);
    *(float4*)(D + i) = v;
}

__global__ __launch_bounds__(256) void round_x(const float* __restrict__ x)
{
    size_t i = ((size_t)blockIdx.x * 256 + threadIdx.x) * 4;
    float4 v = *(const float4*)(x + i);
    v.x = roundtf(v.x); v.y = roundtf(v.y); v.z = roundtf(v.z); v.w = roundtf(v.w);
    *(float4*)(g_Xr + i) = v;
}

// ========== tf32 GEMM: 128x128x32 CTA tile, 4 warps @ 64x64, cp.async 2-stage ==========
// Operands are PRE-ROUNDED tf32-in-fp32 -> no cvt in the inner loop.
#define BM 128
#define BN 128
#define BK 32
#define AS_STRIDE 36
#define BS_STRIDE 136
#define ASTGW (BM * AS_STRIDE)
#define BSTGW (BK * BS_STRIDE)
#define GEMM_SMEM_BYTES ((2 * (ASTGW + BSTGW)) * 4)
#define KITERS (Dm / BK)   // 32

__device__ __forceinline__ void gemm_tf32_body(const float* __restrict__ A,
                                               const float* __restrict__ B,
                                               float* __restrict__ C)
{
    extern __shared__ uint32_t gsm[];
    uint32_t* As = gsm;
    uint32_t* Bs = gsm + 2 * ASTGW;

    const int tid  = threadIdx.x;   // 0..127
    const int lane = tid & 31;
    const int warp = tid >> 5;      // 0..3
    const int wm   = warp >> 1;
    const int wn   = warp & 1;
    const int bM = blockIdx.y * BM;
    const int bN = blockIdx.x * BN;
    const int ar = lane >> 2;
    const int ac = lane & 3;

    const float* Ablk = A + (size_t)bM * Dm;
    const float* Bblk = B + bN;

    float acc[4][8][4];
    #pragma unroll
    for (int mt = 0; mt < 4; mt++)
        #pragma unroll
        for (int nt = 0; nt < 8; nt++)
            #pragma unroll
            for (int i = 0; i < 4; i++) acc[mt][nt][i] = 0.f;

    auto stage = [&](int k0, int buf) {
        uint32_t* Ad = As + buf * ASTGW;
        uint32_t* Bd = Bs + buf * BSTGW;
        #pragma unroll
        for (int i = 0; i < 8; i++) {
            int f   = tid + i * 128;
            int row = f >> 3;
            int c4  = (f & 7) * 4;
            cp16(Ad + row * AS_STRIDE + c4, Ablk + (size_t)row * Dm + k0 + c4);
        }
        #pragma unroll
        for (int i = 0; i < 8; i++) {
            int f    = tid + i * 128;
            int krow = f >> 5;
            int c4   = (f & 31) * 4;
            cp16(Bd + krow * BS_STRIDE + c4, Bblk + (size_t)(k0 + krow) * Dm + c4);
        }
    };

    stage(0, 0);
    CP_COMMIT();

    for (int it = 0; it < KITERS; it++) {
        const int buf = it & 1;
        if (it + 1 < KITERS) stage((it + 1) * BK, buf ^ 1);
        CP_COMMIT();
        CP_WAIT1();
        __syncthreads();

        const uint32_t* Ab = As + buf * ASTGW;
        const uint32_t* Bb = Bs + buf * BSTGW;
        #pragma unroll
        for (int k8 = 0; k8 < BK / 8; k8++) {
            const int k = k8 * 8;
            uint32_t af[4][4];
            #pragma unroll
            for (int mt = 0; mt < 4; mt++) {
                const int mo = wm * 64 + mt * 16;
                af[mt][0] = Ab[(mo + ar    ) * AS_STRIDE + k + ac];
                af[mt][1] = Ab[(mo + ar + 8) * AS_STRIDE + k + ac];
                af[mt][2] = Ab[(mo + ar    ) * AS_STRIDE + k + ac + 4];
                af[mt][3] = Ab[(mo + ar + 8) * AS_STRIDE + k + ac + 4];
            }
            #pragma unroll
            for (int nt = 0; nt < 8; nt++) {
                const int no = wn * 64 + nt * 8;
                uint32_t b0 = Bb[(k + ac    ) * BS_STRIDE + no + ar];
                uint32_t b1 = Bb[(k + ac + 4) * BS_STRIDE + no + ar];
                #pragma unroll
                for (int mt = 0; mt < 4; mt++) {
                    asm volatile(
                        "mma.sync.aligned.m16n8k8.row.col.f32.tf32.tf32.f32 "
                        "{%0,%1,%2,%3}, {%4,%5,%6,%7}, {%8,%9}, {%0,%1,%2,%3};\n"
                        : "+f"(acc[mt][nt][0]), "+f"(acc[mt][nt][1]),
                          "+f"(acc[mt][nt][2]), "+f"(acc[mt][nt][3])
                        : "r"(af[mt][0]), "r"(af[mt][1]),
                          "r"(af[mt][2]), "r"(af[mt][3]),
                          "r"(b0), "r"(b1));
                }
            }
        }
        __syncthreads();
    }

    #pragma unroll
    for (int mt = 0; mt < 4; mt++) {
        const int row0 = bM + wm * 64 + mt * 16 + ar;
        #pragma unroll
        for (int nt = 0; nt < 8; nt++) {
            const int col = bN + wn * 64 + nt * 8 + ac * 2;
            *(float2*)(C + (size_t)row0 * Dm + col)       = make_float2(acc[mt][nt][0], acc[mt][nt][1]);
            *(float2*)(C + (size_t)(row0 + 8) * Dm + col) = make_float2(acc[mt][nt][2], acc[mt][nt][3]);
        }
    }
}

__global__ __launch_bounds__(128, 2) void gemm_qkv()
{
    float* C = (blockIdx.z == 0) ? g_Q : (blockIdx.z == 1) ? g_K : g_V;
    gemm_tf32_body(g_Xr, g_Wr[blockIdx.z], C);
}

__global__ __launch_bounds__(128, 2) void gemm_out(float* __restrict__ out)
{
    gemm_tf32_body(g_ctx, g_Wr[3], out);
}

// ======================= tensor-core causal flash attention =======================
// 256 threads (8 warps); warp w owns 16 query rows. 128 q rows/CTA, key tiles of 64.
// Softmax runs in exp2 domain: Q staged with scale*log2(e) folded in.
#define QS 68
#define KS 68
#define VS 72
#define PS 68
#define ATTN_SMEM_WORDS (128*QS + 64*KS + 64*VS + 128*PS)
#define ATTN_SMEM_BYTES (ATTN_SMEM_WORDS * 4)
#define QSCALE (0.125f * 1.44269504088896f)

__global__ __launch_bounds__(256, 2) void attn_mma()
{
    extern __shared__ uint32_t smw[];
    uint32_t* Qs  = smw;
    uint32_t* Ksm = Qs  + 128 * QS;
    uint32_t* Vsm = Ksm + 64 * KS;
    uint32_t* Psm = Vsm + 64 * VS;

    const int tid  = threadIdx.x;
    const int lane = tid & 31;
    const int warp = tid >> 5;
    const int ar   = lane >> 2;
    const int ac   = lane & 3;

    const int qt = blockIdx.x, h = blockIdx.y, b = blockIdx.z;
    const int q0 = qt * 128;

    const float* Qg = g_Q + ((size_t)(b * Tt + q0)) * Dm + h * Dh;
    #pragma unroll
    for (int i = 0; i < 8; i++) {
        int f = tid + i * 256;
        int row = f >> 4;
        int c4  = (f & 15) * 4;
        float4 v = *(const float4*)(Qg + (size_t)row * Dm + c4);
        uint32_t* d = &Qs[row * QS + c4];
        d[0] = f2tf32(v.x * QSCALE); d[1] = f2tf32(v.y * QSCALE);
        d[2] = f2tf32(v.z * QSCALE); d[3] = f2tf32(v.w * QSCALE);
    }

    float accO[8][4];
    #pragma unroll
    for (int nt = 0; nt < 8; nt++)
        #pragma unroll
        for (int i = 0; i < 4; i++) accO[nt][i] = 0.f;

    float mrow0 = -1e30f, mrow1 = -1e30f, lrow0 = 0.f, lrow1 = 0.f;

    uint32_t* Pw = Psm + warp * 16 * PS;
    const int ntiles = 2 * qt + 2;

    for (int kt = 0; kt < ntiles; kt++) {
        const size_t kvbase = ((size_t)(b * Tt + kt * 64)) * Dm + h * Dh;
        __syncthreads();
        #pragma unroll
        for (int i = 0; i < 4; i++) {
            int f = tid + i * 256;
            int row = f >> 4;
            int c4  = (f & 15) * 4;
            float4 kv = *(const float4*)(g_K + kvbase + (size_t)row * Dm + c4);
            uint32_t* dk = &Ksm[row * KS + c4];
            dk[0] = f2tf32(kv.x); dk[1] = f2tf32(kv.y);
            dk[2] = f2tf32(kv.z); dk[3] = f2tf32(kv.w);
            float4 vv = *(const float4*)(g_V + kvbase + (size_t)row * Dm + c4);
            uint32_t* dv = &Vsm[row * VS + c4];
            dv[0] = f2tf32(vv.x); dv[1] = f2tf32(vv.y);
            dv[2] = f2tf32(vv.z); dv[3] = f2tf32(vv.w);
        }
        __syncthreads();

        float s[8][4];
        #pragma unroll
        for (int nt = 0; nt < 8; nt++)
            #pragma unroll
            for (int i = 0; i < 4; i++) s[nt][i] = 0.f;

        #pragma unroll
        for (int k8 = 0; k8 < 8; k8++) {
            const int k = k8 * 8;
            const int mo = warp * 16;
            uint32_t a0 = Qs[(mo + ar    ) * QS + k + ac];
            uint32_t a1 = Qs[(mo + ar + 8) * QS + k + ac];
            uint32_t a2 = Qs[(mo + ar    ) * QS + k + ac + 4];
            uint32_t a3 = Qs[(mo + ar + 8) * QS + k + ac + 4];
            #pragma unroll
            for (int nt = 0; nt < 8; nt++) {
                const int n = nt * 8;
                uint32_t b0 = Ksm[(n + ar) * KS + k + ac];
                uint32_t b1 = Ksm[(n + ar) * KS + k + ac + 4];
                asm volatile(
                    "mma.sync.aligned.m16n8k8.row.col.f32.tf32.tf32.f32 "
                    "{%0,%1,%2,%3}, {%4,%5,%6,%7}, {%8,%9}, {%0,%1,%2,%3};\n"
                    : "+f"(s[nt][0]), "+f"(s[nt][1]), "+f"(s[nt][2]), "+f"(s[nt][3])
                    : "r"(a0), "r"(a1), "r"(a2), "r"(a3), "r"(b0), "r"(b1));
            }
        }

        const int r0 = q0 + warp * 16 + ar;
        if (kt >= 2 * qt) {
            #pragma unroll
            for (int nt = 0; nt < 8; nt++) {
                const int c0 = kt * 64 + nt * 8 + 2 * ac;
                if (c0     > r0    ) s[nt][0] = -1e30f;
                if (c0 + 1 > r0    ) s[nt][1] = -1e30f;
                if (c0     > r0 + 8) s[nt][2] = -1e30f;
                if (c0 + 1 > r0 + 8) s[nt][3] = -1e30f;
            }
        }
        float mx0 = -1e30f, mx1 = -1e30f;
        #pragma unroll
        for (int nt = 0; nt < 8; nt++) {
            mx0 = fmaxf(mx0, fmaxf(s[nt][0], s[nt][1]));
            mx1 = fmaxf(mx1, fmaxf(s[nt][2], s[nt][3]));
        }
        mx0 = fmaxf(mx0, __shfl_xor_sync(0xffffffff, mx0, 1));
        mx0 = fmaxf(mx0, __shfl_xor_sync(0xffffffff, mx0, 2));
        mx1 = fmaxf(mx1, __shfl_xor_sync(0xffffffff, mx1, 1));
        mx1 = fmaxf(mx1, __shfl_xor_sync(0xffffffff, mx1, 2));

        const float mn0 = fmaxf(mrow0, mx0);
        const float mn1 = fmaxf(mrow1, mx1);
        const float corr0 = ex2f(mrow0 - mn0);
        const float corr1 = ex2f(mrow1 - mn1);
        mrow0 = mn0; mrow1 = mn1;

        float ls0 = 0.f, ls1 = 0.f;
        #pragma unroll
        for (int nt = 0; nt < 8; nt++) {
            float p00 = ex2f(s[nt][0] - mn0);
            float p01 = ex2f(s[nt][1] - mn0);
            float p10 = ex2f(s[nt][2] - mn1);
            float p11 = ex2f(s[nt][3] - mn1);
            ls0 += p00 + p01;
            ls1 += p10 + p11;
            uint32_t* pw = Pw + ar * PS + nt * 8 + 2 * ac;
            pw[0]          = f2tf32(p00);
            pw[1]          = f2tf32(p01);
            pw[8 * PS]     = f2tf32(p10);
            pw[8 * PS + 1] = f2tf32(p11);
        }
        ls0 += __shfl_xor_sync(0xffffffff, ls0, 1);
        ls0 += __shfl_xor_sync(0xffffffff, ls0, 2);
        ls1 += __shfl_xor_sync(0xffffffff, ls1, 1);
        ls1 += __shfl_xor_sync(0xffffffff, ls1, 2);
        lrow0 = lrow0 * corr0 + ls0;
        lrow1 = lrow1 * corr1 + ls1;

        #pragma unroll
        for (int nt = 0; nt < 8; nt++) {
            accO[nt][0] *= corr0; accO[nt][1] *= corr0;
            accO[nt][2] *= corr1; accO[nt][3] *= corr1;
        }
        __syncwarp();

        #pragma unroll
        for (int k8 = 0; k8 < 8; k8++) {
            const int k = k8 * 8;
            uint32_t a0 = Pw[(ar    ) * PS + k + ac];
            uint32_t a1 = Pw[(ar + 8) * PS + k + ac];
            uint32_t a2 = Pw[(ar    ) * PS + k + ac + 4];
            uint32_t a3 = Pw[(ar + 8) * PS + k + ac + 4];
            #pragma unroll
            for (int nt = 0; nt < 8; nt++) {
                const int n = nt * 8;
                uint32_t b0 = Vsm[(k + ac    ) * VS + n + ar];
                uint32_t b1 = Vsm[(k + ac + 4) * VS + n + ar];
                asm volatile(
                    "mma.sync.aligned.m16n8k8.row.col.f32.tf32.tf32.f32 "
                    "{%0,%1,%2,%3}, {%4,%5,%6,%7}, {%8,%9}, {%0,%1,%2,%3};\n"
                    : "+f"(accO[nt][0]), "+f"(accO[nt][1]),
                      "+f"(accO[nt][2]), "+f"(accO[nt][3])
                    : "r"(a0), "r"(a1), "r"(a2), "r"(a3), "r"(b0), "r"(b1));
            }
        }
    }

    // normalize + store, tf32-rounded so gemm_out needs no cvt
    const float inv0 = 1.f / lrow0;
    const float inv1 = 1.f / lrow1;
    const int r0 = q0 + warp * 16 + ar;
    float* og = g_ctx + ((size_t)(b * Tt)) * Dm + h * Dh;
    #pragma unroll
    for (int nt = 0; nt < 8; nt++) {
        const int col = nt * 8 + 2 * ac;
        *(float2*)(og + (size_t)r0 * Dm + col) =
            make_float2(roundtf(accO[nt][0] * inv0), roundtf(accO[nt][1] * inv0));
        *(float2*)(og + (size_t)(r0 + 8) * Dm + col) =
            make_float2(roundtf(accO[nt][2] * inv1), roundtf(accO[nt][3] * inv1));
    }
}

// ======================= launch =======================
extern "C" void kernel_launch(void* const* d_in, const int* in_sizes, int n_in,
                              void* d_out, int out_size)
{
    const float* x  = (const float*)d_in[0];
    const float* Wq = (const float*)d_in[1];
    const float* Wk = (const float*)d_in[2];
    const float* Wv = (const float*)d_in[3];
    const float* Wo = (const float*)d_in[4];
    float* out = (float*)d_out;

    cudaFuncSetAttribute(gemm_qkv, cudaFuncAttributeMaxDynamicSharedMemorySize, GEMM_SMEM_BYTES);
    cudaFuncSetAttribute(gemm_out, cudaFuncAttributeMaxDynamicSharedMemorySize, GEMM_SMEM_BYTES);
    cudaFuncSetAttribute(attn_mma, cudaFuncAttributeMaxDynamicSharedMemorySize, ATTN_SMEM_BYTES);

    round_w<<<dim3((Dm * Dm / 4) / 256, 1, 4), 256>>>(Wq, Wk, Wv, Wo);
    round_x<<<(Mrows * Dm / 4) / 256, 256>>>(x);

    gemm_qkv<<<dim3(Dm / BN, Mrows / BM, 3), 128, GEMM_SMEM_BYTES>>>();

    attn_mma<<<dim3(Tt / 128, Hh, Bz), 256, ATTN_SMEM_BYTES>>>();

    gemm_out<<<dim3(Dm / BN, Mrows / BM, 1), 128, GEMM_SMEM_BYTES>>>(out);
}

// round 11
// speedup vs baseline: 4.4013x; 2.1234x over previous
#include <cuda_runtime.h>
#include <cuda_fp16.h>
#include <math.h>
#include <stdint.h>

#define Bz     4
#define Tt     2048
#define Dm     1024
#define Hh     16
#define Dh     64
#define Mrows  (Bz * Tt)     // 8192
#define QSCALE (0.125f * 1.44269504088896f)

// ---- scratch (fp16 data plane) ----
__device__ __half g_Xh[Mrows * Dm];
__device__ __half g_Wh[4][Dm * Dm];
__device__ __half g_Qh[Mrows * Dm];   // pre-scaled by QSCALE
__device__ __half g_Kh[Mrows * Dm];
__device__ __half g_Vh[Mrows * Dm];
__device__ __half g_ctxh[Mrows * Dm];

__device__ __forceinline__ uint32_t pack_h2(float a, float b) {
    __half2 h = __floats2half2_rn(a, b);
    return *(uint32_t*)&h;
}
__device__ __forceinline__ float ex2f(float x) {
    float r;
    asm("ex2.approx.ftz.f32 %0, %1;" : "=f"(r) : "f"(x));
    return r;
}
__device__ __forceinline__ uint32_t smem_u32(const void* p) {
    return (uint32_t)__cvta_generic_to_shared(p);
}
__device__ __forceinline__ void cp16(uint32_t dst_smem, const void* src) {
    asm volatile("cp.async.cg.shared.global [%0], [%1], 16;\n" :: "r"(dst_smem), "l"(src));
}
#define CP_COMMIT() asm volatile("cp.async.commit_group;\n" ::: "memory")
#define CP_WAIT1()  asm volatile("cp.async.wait_group 1;\n" ::: "memory")
#define CP_WAIT0()  asm volatile("cp.async.wait_group 0;\n" ::: "memory")

#define LDMX4(r0,r1,r2,r3,addr) \
    asm volatile("ldmatrix.sync.aligned.m8n8.x4.shared.b16 {%0,%1,%2,%3}, [%4];" \
        : "=r"(r0),"=r"(r1),"=r"(r2),"=r"(r3) : "r"(addr))
#define LDMX4T(r0,r1,r2,r3,addr) \
    asm volatile("ldmatrix.sync.aligned.m8n8.x4.trans.shared.b16 {%0,%1,%2,%3}, [%4];" \
        : "=r"(r0),"=r"(r1),"=r"(r2),"=r"(r3) : "r"(addr))
#define MMA16816(acc,a,b0,b1) \
    asm volatile("mma.sync.aligned.m16n8k16.row.col.f32.f16.f16.f32 " \
        "{%0,%1,%2,%3}, {%4,%5,%6,%7}, {%8,%9}, {%0,%1,%2,%3};\n" \
        : "+f"((acc)[0]), "+f"((acc)[1]), "+f"((acc)[2]), "+f"((acc)[3]) \
        : "r"((a)[0]), "r"((a)[1]), "r"((a)[2]), "r"((a)[3]), "r"(b0), "r"(b1))

// ======================= prep: fp32 -> fp16 =======================
__global__ __launch_bounds__(256) void prep_w(const float* __restrict__ Wq,
                                              const float* __restrict__ Wk,
                                              const float* __restrict__ Wv,
                                              const float* __restrict__ Wo)
{
    const float* W = (blockIdx.z == 0) ? Wq : (blockIdx.z == 1) ? Wk :
                     (blockIdx.z == 2) ? Wv : Wo;
    __half* D = g_Wh[blockIdx.z];
    size_t i = ((size_t)blockIdx.x * 256 + threadIdx.x) * 4;
    float4 v = *(const float4*)(W + i);
    uint2 o = make_uint2(pack_h2(v.x, v.y), pack_h2(v.z, v.w));
    *(uint2*)&D[i] = o;
}
__global__ __launch_bounds__(256) void prep_x(const float* __restrict__ x)
{
    size_t i = ((size_t)blockIdx.x * 256 + threadIdx.x) * 4;
    float4 v = *(const float4*)(x + i);
    *(uint2*)&g_Xh[i] = make_uint2(pack_h2(v.x, v.y), pack_h2(v.z, v.w));
}

// ========== fp16 GEMM: 128x128x32 CTA tile, 4 warps @ 64x64, cp.async 2-stage ==========
// A smem [128][40 halves] (80B rows), B smem [32][152 halves] (304B rows)
#define GA_STRIDE_B 80
#define GB_STRIDE_B 304
#define GA_BYTES (128 * GA_STRIDE_B)   // 10240
#define GB_BYTES (32 * GB_STRIDE_B)    // 9728
#define GSTG (GA_BYTES + GB_BYTES)
#define GEMM_SMEM_BYTES (2 * GSTG)     // 39936
#define KITERS (Dm / 32)

// mode: 0..2 = store half to g_Q/K/Vh (0 with QSCALE); 3 = store float to Cf
__device__ __forceinline__ void gemm_f16_body(const __half* __restrict__ Ah,
                                              const __half* __restrict__ Bh,
                                              int mode, float* __restrict__ Cf)
{
    extern __shared__ __align__(16) char smem[];
    const uint32_t smb = smem_u32(smem);

    const int tid  = threadIdx.x;   // 0..127
    const int lane = tid & 31;
    const int warp = tid >> 5;
    const int wm   = warp >> 1;
    const int wn   = warp & 1;
    const int bM = blockIdx.y * 128;
    const int bN = blockIdx.x * 128;
    const int j  = lane >> 3;       // ldmatrix matrix index
    const int l7 = lane & 7;

    const __half* Ab = Ah + (size_t)bM * Dm;
    const __half* Bb = Bh + bN;

    float acc[4][8][4];
    #pragma unroll
    for (int mt = 0; mt < 4; mt++)
        #pragma unroll
        for (int nt = 0; nt < 8; nt++)
            #pragma unroll
            for (int i = 0; i < 4; i++) acc[mt][nt][i] = 0.f;

    auto stage = [&](int k0, int buf) {
        const uint32_t Ad = smb + buf * GSTG;
        const uint32_t Bd = Ad + GA_BYTES;
        #pragma unroll
        for (int i = 0; i < 4; i++) {
            int f = tid + i * 128;
            cp16(Ad + (f >> 2) * GA_STRIDE_B + (f & 3) * 16,
                 Ab + (size_t)(f >> 2) * Dm + k0 + (f & 3) * 8);
            cp16(Bd + (f >> 4) * GB_STRIDE_B + (f & 15) * 16,
                 Bb + (size_t)(k0 + (f >> 4)) * Dm + (f & 15) * 8);
        }
    };

    stage(0, 0);
    CP_COMMIT();

    for (int it = 0; it < KITERS; it++) {
        const int buf = it & 1;
        if (it + 1 < KITERS) stage((it + 1) * 32, buf ^ 1);
        CP_COMMIT();
        CP_WAIT1();
        __syncthreads();

        const uint32_t Ad = smb + buf * GSTG;
        const uint32_t Bd = Ad + GA_BYTES;
        #pragma unroll
        for (int ks = 0; ks < 2; ks++) {
            uint32_t af[4][4];
            #pragma unroll
            for (int mt = 0; mt < 4; mt++) {
                uint32_t a = Ad + (uint32_t)(wm * 64 + mt * 16 + (j & 1) * 8 + l7) * GA_STRIDE_B
                           + (ks * 16 + (j >> 1) * 8) * 2;
                LDMX4(af[mt][0], af[mt][1], af[mt][2], af[mt][3], a);
            }
            #pragma unroll
            for (int pr = 0; pr < 4; pr++) {
                uint32_t b0, b1, b2, b3;
                uint32_t a = Bd + (uint32_t)(ks * 16 + (j & 1) * 8 + l7) * GB_STRIDE_B
                           + (wn * 64 + pr * 16 + (j >> 1) * 8) * 2;
                LDMX4T(b0, b1, b2, b3, a);
                #pragma unroll
                for (int mt = 0; mt < 4; mt++) {
                    MMA16816(acc[mt][2 * pr],     af[mt], b0, b1);
                    MMA16816(acc[mt][2 * pr + 1], af[mt], b2, b3);
                }
            }
        }
        __syncthreads();
    }

    const int ar = lane >> 2;
    const int ac = lane & 3;
    const float sc = (mode == 0) ? QSCALE : 1.f;
    #pragma unroll
    for (int mt = 0; mt < 4; mt++) {
        const int row0 = bM + wm * 64 + mt * 16 + ar;
        #pragma unroll
        for (int nt = 0; nt < 8; nt++) {
            const int col = bN + wn * 64 + nt * 8 + ac * 2;
            if (mode == 3) {
                *(float2*)(Cf + (size_t)row0 * Dm + col)       = make_float2(acc[mt][nt][0], acc[mt][nt][1]);
                *(float2*)(Cf + (size_t)(row0 + 8) * Dm + col) = make_float2(acc[mt][nt][2], acc[mt][nt][3]);
            } else {
                __half* Ch = (mode == 0) ? g_Qh : (mode == 1) ? g_Kh : g_Vh;
                *(uint32_t*)&Ch[(size_t)row0 * Dm + col] =
                    pack_h2(acc[mt][nt][0] * sc, acc[mt][nt][1] * sc);
                *(uint32_t*)&Ch[(size_t)(row0 + 8) * Dm + col] =
                    pack_h2(acc[mt][nt][2] * sc, acc[mt][nt][3] * sc);
            }
        }
    }
}

__global__ __launch_bounds__(128, 2) void gemm_qkv()
{
    gemm_f16_body(g_Xh, g_Wh[blockIdx.z], (int)blockIdx.z, nullptr);
}
__global__ __launch_bounds__(128, 2) void gemm_out(float* __restrict__ out)
{
    gemm_f16_body(g_ctxh, g_Wh[3], 3, out);
}

// ======================= fp16 tensor-core causal flash attention =======================
// 256 threads (8 warps); warp w owns 16 query rows; 128 q rows/CTA; key tiles of 64.
// Q/K/V smem rows padded to 72 halves (144B). P stays in registers (C->A frag identity).
#define AT_STRIDE_B 144
#define AQ_BYTES (128 * AT_STRIDE_B)   // 18432
#define AK_BYTES (64 * AT_STRIDE_B)    // 9216
#define ATTN_SMEM_BYTES (AQ_BYTES + 2 * AK_BYTES)   // 36864

__global__ __launch_bounds__(256, 2) void attn_mma()
{
    extern __shared__ __align__(16) char smem[];
    const uint32_t smQ = smem_u32(smem);
    const uint32_t smK = smQ + AQ_BYTES;
    const uint32_t smV = smK + AK_BYTES;

    const int tid  = threadIdx.x;
    const int lane = tid & 31;
    const int warp = tid >> 5;
    const int ar   = lane >> 2;
    const int ac   = lane & 3;
    const int j    = lane >> 3;
    const int l7   = lane & 7;

    const int qt = blockIdx.x, h = blockIdx.y, b = blockIdx.z;
    const int q0 = qt * 128;

    // ---- stage Q (fp16, pre-scaled) ----
    const __half* Qg = g_Qh + ((size_t)(b * Tt + q0)) * Dm + h * Dh;
    #pragma unroll
    for (int i = 0; i < 4; i++) {
        int f = tid + i * 256;              // 1024 16B-chunks
        cp16(smQ + (f >> 3) * AT_STRIDE_B + (f & 7) * 16,
             Qg + (size_t)(f >> 3) * Dm + (f & 7) * 8);
    }
    CP_COMMIT();

    float accO[8][4];
    #pragma unroll
    for (int nt = 0; nt < 8; nt++)
        #pragma unroll
        for (int i = 0; i < 4; i++) accO[nt][i] = 0.f;

    float mrow0 = -1e30f, mrow1 = -1e30f, lrow0 = 0.f, lrow1 = 0.f;
    const int ntiles = 2 * qt + 2;

    for (int kt = 0; kt < ntiles; kt++) {
        const __half* Kg = g_Kh + ((size_t)(b * Tt + kt * 64)) * Dm + h * Dh;
        const __half* Vg = g_Vh + ((size_t)(b * Tt + kt * 64)) * Dm + h * Dh;
        __syncthreads();                    // protect previous tile reads
        #pragma unroll
        for (int i = 0; i < 2; i++) {
            int f = tid + i * 256;          // 512 chunks each
            cp16(smK + (f >> 3) * AT_STRIDE_B + (f & 7) * 16,
                 Kg + (size_t)(f >> 3) * Dm + (f & 7) * 8);
            cp16(smV + (f >> 3) * AT_STRIDE_B + (f & 7) * 16,
                 Vg + (size_t)(f >> 3) * Dm + (f & 7) * 8);
        }
        CP_COMMIT();
        CP_WAIT0();
        __syncthreads();

        // ---- S = Q K^T (warp: 16 x 64), 4 ksteps of k16 ----
        float s[8][4];
        #pragma unroll
        for (int nt = 0; nt < 8; nt++)
            #pragma unroll
            for (int i = 0; i < 4; i++) s[nt][i] = 0.f;

        #pragma unroll
        for (int ks = 0; ks < 4; ks++) {
            uint32_t qa[4];
            uint32_t aq = smQ + (uint32_t)(warp * 16 + (j & 1) * 8 + l7) * AT_STRIDE_B
                        + (ks * 16 + (j >> 1) * 8) * 2;
            LDMX4(qa[0], qa[1], qa[2], qa[3], aq);
            #pragma unroll
            for (int pr = 0; pr < 4; pr++) {
                uint32_t b0, b1, b2, b3;
                uint32_t akd = smK + (uint32_t)(pr * 16 + (j >> 1) * 8 + l7) * AT_STRIDE_B
                             + (ks * 16 + (j & 1) * 8) * 2;
                LDMX4(b0, b1, b2, b3, akd);
                MMA16816(s[2 * pr],     qa, b0, b1);
                MMA16816(s[2 * pr + 1], qa, b2, b3);
            }
        }

        // ---- mask + online softmax (log2 domain; QSCALE already folded) ----
        const int r0 = q0 + warp * 16 + ar;
        if (kt >= 2 * qt) {
            #pragma unroll
            for (int nt = 0; nt < 8; nt++) {
                const int c0 = kt * 64 + nt * 8 + 2 * ac;
                if (c0     > r0    ) s[nt][0] = -1e30f;
                if (c0 + 1 > r0    ) s[nt][1] = -1e30f;
                if (c0     > r0 + 8) s[nt][2] = -1e30f;
                if (c0 + 1 > r0 + 8) s[nt][3] = -1e30f;
            }
        }
        float mx0 = -1e30f, mx1 = -1e30f;
        #pragma unroll
        for (int nt = 0; nt < 8; nt++) {
            mx0 = fmaxf(mx0, fmaxf(s[nt][0], s[nt][1]));
            mx1 = fmaxf(mx1, fmaxf(s[nt][2], s[nt][3]));
        }
        mx0 = fmaxf(mx0, __shfl_xor_sync(0xffffffff, mx0, 1));
        mx0 = fmaxf(mx0, __shfl_xor_sync(0xffffffff, mx0, 2));
        mx1 = fmaxf(mx1, __shfl_xor_sync(0xffffffff, mx1, 1));
        mx1 = fmaxf(mx1, __shfl_xor_sync(0xffffffff, mx1, 2));

        const float mn0 = fmaxf(mrow0, mx0);
        const float mn1 = fmaxf(mrow1, mx1);
        const float corr0 = ex2f(mrow0 - mn0);
        const float corr1 = ex2f(mrow1 - mn1);
        mrow0 = mn0; mrow1 = mn1;

        uint32_t ph[8][2];
        float ls0 = 0.f, ls1 = 0.f;
        #pragma unroll
        for (int nt = 0; nt < 8; nt++) {
            float p00 = ex2f(s[nt][0] - mn0);
            float p01 = ex2f(s[nt][1] - mn0);
            float p10 = ex2f(s[nt][2] - mn1);
            float p11 = ex2f(s[nt][3] - mn1);
            ls0 += p00 + p01;
            ls1 += p10 + p11;
            ph[nt][0] = pack_h2(p00, p01);
            ph[nt][1] = pack_h2(p10, p11);
        }
        ls0 += __shfl_xor_sync(0xffffffff, ls0, 1);
        ls0 += __shfl_xor_sync(0xffffffff, ls0, 2);
        ls1 += __shfl_xor_sync(0xffffffff, ls1, 1);
        ls1 += __shfl_xor_sync(0xffffffff, ls1, 2);
        lrow0 = lrow0 * corr0 + ls0;
        lrow1 = lrow1 * corr1 + ls1;

        #pragma unroll
        for (int nt = 0; nt < 8; nt++) {
            accO[nt][0] *= corr0; accO[nt][1] *= corr0;
            accO[nt][2] *= corr1; accO[nt][3] *= corr1;
        }

        // ---- O += P V : P from registers (C->A frag identity), V via ldmatrix.trans ----
        #pragma unroll
        for (int jk = 0; jk < 4; jk++) {
            uint32_t pa[4] = { ph[2 * jk][0], ph[2 * jk][1], ph[2 * jk + 1][0], ph[2 * jk + 1][1] };
            #pragma unroll
            for (int pr = 0; pr < 4; pr++) {
                uint32_t v0, v1, v2, v3;
                uint32_t av = smV + (uint32_t)(jk * 16 + (j & 1) * 8 + l7) * AT_STRIDE_B
                            + (pr * 16 + (j >> 1) * 8) * 2;
                LDMX4T(v0, v1, v2, v3, av);
                MMA16816(accO[2 * pr],     pa, v0, v1);
                MMA16816(accO[2 * pr + 1], pa, v2, v3);
            }
        }
    }

    // ---- normalize + store ctx as fp16 ----
    const float inv0 = 1.f / lrow0;
    const float inv1 = 1.f / lrow1;
    const int r0 = q0 + warp * 16 + ar;
    __half* og = g_ctxh + ((size_t)(b * Tt)) * Dm + h * Dh;
    #pragma unroll
    for (int nt = 0; nt < 8; nt++) {
        const int col = nt * 8 + 2 * ac;
        *(uint32_t*)&og[(size_t)r0 * Dm + col] =
            pack_h2(accO[nt][0] * inv0, accO[nt][1] * inv0);
        *(uint32_t*)&og[(size_t)(r0 + 8) * Dm + col] =
            pack_h2(accO[nt][2] * inv1, accO[nt][3] * inv1);
    }
}

// ======================= launch =======================
extern "C" void kernel_launch(void* const* d_in, const int* in_sizes, int n_in,
                              void* d_out, int out_size)
{
    const float* x  = (const float*)d_in[0];
    const float* Wq = (const float*)d_in[1];
    const float* Wk = (const float*)d_in[2];
    const float* Wv = (const float*)d_in[3];
    const float* Wo = (const float*)d_in[4];
    float* out = (float*)d_out;

    cudaFuncSetAttribute(gemm_qkv, cudaFuncAttributeMaxDynamicSharedMemorySize, GEMM_SMEM_BYTES);
    cudaFuncSetAttribute(gemm_out, cudaFuncAttributeMaxDynamicSharedMemorySize, GEMM_SMEM_BYTES);
    cudaFuncSetAttribute(attn_mma, cudaFuncAttributeMaxDynamicSharedMemorySize, ATTN_SMEM_BYTES);

    prep_w<<<dim3((Dm * Dm / 4) / 256, 1, 4), 256>>>(Wq, Wk, Wv, Wo);
    prep_x<<<(Mrows * Dm / 4) / 256, 256>>>(x);

    gemm_qkv<<<dim3(Dm / 128, Mrows / 128, 3), 128, GEMM_SMEM_BYTES>>>();

    attn_mma<<<dim3(Tt / 128, Hh, Bz), 256, ATTN_SMEM_BYTES>>>();

    gemm_out<<<dim3(Dm / 128, Mrows / 128, 1), 128, GEMM_SMEM_BYTES>>>(out);
}

// round 14
// speedup vs baseline: 4.5954x; 1.0441x over previous
#include <cuda_runtime.h>
#include <cuda_fp16.h>
#include <math.h>
#include <stdint.h>

#define Bz     4
#define Tt     2048
#define Dm     1024
#define Hh     16
#define Dh     64
#define Mrows  (Bz * Tt)     // 8192
#define QSCALE (0.125f * 1.44269504088896f)

// ---- scratch (fp16 data plane) ----
__device__ __half g_Xh[Mrows * Dm];
__device__ __half g_Wh[4][Dm * Dm];
__device__ __half g_Qh[Mrows * Dm];   // pre-scaled by QSCALE
__device__ __half g_Kh[Mrows * Dm];
__device__ __half g_Vh[Mrows * Dm];
__device__ __half g_ctxh[Mrows * Dm];

__device__ __forceinline__ uint32_t pack_h2(float a, float b) {
    __half2 h = __floats2half2_rn(a, b);
    return *(uint32_t*)&h;
}
__device__ __forceinline__ float ex2f(float x) {
    float r;
    asm("ex2.approx.ftz.f32 %0, %1;" : "=f"(r) : "f"(x));
    return r;
}
__device__ __forceinline__ uint32_t smem_u32(const void* p) {
    return (uint32_t)__cvta_generic_to_shared(p);
}
__device__ __forceinline__ void cp16(uint32_t dst_smem, const void* src) {
    asm volatile("cp.async.cg.shared.global [%0], [%1], 16;\n" :: "r"(dst_smem), "l"(src));
}
#define CP_COMMIT() asm volatile("cp.async.commit_group;\n" ::: "memory")
#define CP_WAIT1()  asm volatile("cp.async.wait_group 1;\n" ::: "memory")
#define CP_WAIT0()  asm volatile("cp.async.wait_group 0;\n" ::: "memory")

#define LDMX4(r0,r1,r2,r3,addr) \
    asm volatile("ldmatrix.sync.aligned.m8n8.x4.shared.b16 {%0,%1,%2,%3}, [%4];" \
        : "=r"(r0),"=r"(r1),"=r"(r2),"=r"(r3) : "r"(addr))
#define LDMX4T(r0,r1,r2,r3,addr) \
    asm volatile("ldmatrix.sync.aligned.m8n8.x4.trans.shared.b16 {%0,%1,%2,%3}, [%4];" \
        : "=r"(r0),"=r"(r1),"=r"(r2),"=r"(r3) : "r"(addr))
#define MMA16816(acc,a,b0,b1) \
    asm volatile("mma.sync.aligned.m16n8k16.row.col.f32.f16.f16.f32 " \
        "{%0,%1,%2,%3}, {%4,%5,%6,%7}, {%8,%9}, {%0,%1,%2,%3};\n" \
        : "+f"((acc)[0]), "+f"((acc)[1]), "+f"((acc)[2]), "+f"((acc)[3]) \
        : "r"((a)[0]), "r"((a)[1]), "r"((a)[2]), "r"((a)[3]), "r"(b0), "r"(b1))

// ======================= prep: fp32 -> fp16 =======================
__global__ __launch_bounds__(256) void prep_w(const float* __restrict__ Wq,
                                              const float* __restrict__ Wk,
                                              const float* __restrict__ Wv,
                                              const float* __restrict__ Wo)
{
    const float* W = (blockIdx.z == 0) ? Wq : (blockIdx.z == 1) ? Wk :
                     (blockIdx.z == 2) ? Wv : Wo;
    __half* D = g_Wh[blockIdx.z];
    size_t i = ((size_t)blockIdx.x * 256 + threadIdx.x) * 4;
    float4 v = *(const float4*)(W + i);
    uint2 o = make_uint2(pack_h2(v.x, v.y), pack_h2(v.z, v.w));
    *(uint2*)&D[i] = o;
}
__global__ __launch_bounds__(256) void prep_x(const float* __restrict__ x)
{
    size_t i = ((size_t)blockIdx.x * 256 + threadIdx.x) * 4;
    float4 v = *(const float4*)(x + i);
    *(uint2*)&g_Xh[i] = make_uint2(pack_h2(v.x, v.y), pack_h2(v.z, v.w));
}

// ========== fp16 GEMM: 128x128x32 CTA tile, 4 warps @ 64x64, cp.async 2-stage ==========
#define GA_STRIDE_B 80
#define GB_STRIDE_B 304
#define GA_BYTES (128 * GA_STRIDE_B)   // 10240
#define GB_BYTES (32 * GB_STRIDE_B)    // 9728
#define GSTG (GA_BYTES + GB_BYTES)
#define GEMM_SMEM_BYTES (2 * GSTG)     // 39936
#define KITERS (Dm / 32)

__device__ __forceinline__ void gemm_f16_body(const __half* __restrict__ Ah,
                                              const __half* __restrict__ Bh,
                                              int mode, float* __restrict__ Cf)
{
    extern __shared__ __align__(16) char smem[];
    const uint32_t smb = smem_u32(smem);

    const int tid  = threadIdx.x;   // 0..127
    const int lane = tid & 31;
    const int warp = tid >> 5;
    const int wm   = warp >> 1;
    const int wn   = warp & 1;
    const int bM = blockIdx.y * 128;
    const int bN = blockIdx.x * 128;
    const int j  = lane >> 3;
    const int l7 = lane & 7;

    const __half* Ab = Ah + (size_t)bM * Dm;
    const __half* Bb = Bh + bN;

    float acc[4][8][4];
    #pragma unroll
    for (int mt = 0; mt < 4; mt++)
        #pragma unroll
        for (int nt = 0; nt < 8; nt++)
            #pragma unroll
            for (int i = 0; i < 4; i++) acc[mt][nt][i] = 0.f;

    auto stage = [&](int k0, int buf) {
        const uint32_t Ad = smb + buf * GSTG;
        const uint32_t Bd = Ad + GA_BYTES;
        #pragma unroll
        for (int i = 0; i < 4; i++) {
            int f = tid + i * 128;
            cp16(Ad + (f >> 2) * GA_STRIDE_B + (f & 3) * 16,
                 Ab + (size_t)(f >> 2) * Dm + k0 + (f & 3) * 8);
            cp16(Bd + (f >> 4) * GB_STRIDE_B + (f & 15) * 16,
                 Bb + (size_t)(k0 + (f >> 4)) * Dm + (f & 15) * 8);
        }
    };

    stage(0, 0);
    CP_COMMIT();

    for (int it = 0; it < KITERS; it++) {
        const int buf = it & 1;
        if (it + 1 < KITERS) stage((it + 1) * 32, buf ^ 1);
        CP_COMMIT();
        CP_WAIT1();
        __syncthreads();

        const uint32_t Ad = smb + buf * GSTG;
        const uint32_t Bd = Ad + GA_BYTES;
        #pragma unroll
        for (int ks = 0; ks < 2; ks++) {
            uint32_t af[4][4];
            #pragma unroll
            for (int mt = 0; mt < 4; mt++) {
                uint32_t a = Ad + (uint32_t)(wm * 64 + mt * 16 + (j & 1) * 8 + l7) * GA_STRIDE_B
                           + (ks * 16 + (j >> 1) * 8) * 2;
                LDMX4(af[mt][0], af[mt][1], af[mt][2], af[mt][3], a);
            }
            #pragma unroll
            for (int pr = 0; pr < 4; pr++) {
                uint32_t b0, b1, b2, b3;
                uint32_t a = Bd + (uint32_t)(ks * 16 + (j & 1) * 8 + l7) * GB_STRIDE_B
                           + (wn * 64 + pr * 16 + (j >> 1) * 8) * 2;
                LDMX4T(b0, b1, b2, b3, a);
                #pragma unroll
                for (int mt = 0; mt < 4; mt++) {
                    MMA16816(acc[mt][2 * pr],     af[mt], b0, b1);
                    MMA16816(acc[mt][2 * pr + 1], af[mt], b2, b3);
                }
            }
        }
        __syncthreads();
    }

    const int ar = lane >> 2;
    const int ac = lane & 3;
    const float sc = (mode == 0) ? QSCALE : 1.f;
    #pragma unroll
    for (int mt = 0; mt < 4; mt++) {
        const int row0 = bM + wm * 64 + mt * 16 + ar;
        #pragma unroll
        for (int nt = 0; nt < 8; nt++) {
            const int col = bN + wn * 64 + nt * 8 + ac * 2;
            if (mode == 3) {
                *(float2*)(Cf + (size_t)row0 * Dm + col)       = make_float2(acc[mt][nt][0], acc[mt][nt][1]);
                *(float2*)(Cf + (size_t)(row0 + 8) * Dm + col) = make_float2(acc[mt][nt][2], acc[mt][nt][3]);
            } else {
                __half* Ch = (mode == 0) ? g_Qh : (mode == 1) ? g_Kh : g_Vh;
                *(uint32_t*)&Ch[(size_t)row0 * Dm + col] =
                    pack_h2(acc[mt][nt][0] * sc, acc[mt][nt][1] * sc);
                *(uint32_t*)&Ch[(size_t)(row0 + 8) * Dm + col] =
                    pack_h2(acc[mt][nt][2] * sc, acc[mt][nt][3] * sc);
            }
        }
    }
}

__global__ __launch_bounds__(128, 2) void gemm_qkv()
{
    gemm_f16_body(g_Xh, g_Wh[blockIdx.z], (int)blockIdx.z, nullptr);
}
__global__ __launch_bounds__(128, 2) void gemm_out(float* __restrict__ out)
{
    gemm_f16_body(g_ctxh, g_Wh[3], 3, out);
}

// ======================= fp16 causal flash attention, double-buffered K/V =======================
// 256 threads (8 warps); warp w owns 16 query rows; 128 q rows/CTA; key tiles of 64.
#define AT_STRIDE_B 144
#define AQ_BYTES (128 * AT_STRIDE_B)   // 18432
#define AK_BYTES (64 * AT_STRIDE_B)    // 9216
#define ATTN_SMEM_BYTES (AQ_BYTES + 4 * AK_BYTES)   // 55296 (Q + 2x (K+V))

__global__ __launch_bounds__(256, 2) void attn_mma()
{
    extern __shared__ __align__(16) char smem[];
    const uint32_t smQ = smem_u32(smem);

    const int tid  = threadIdx.x;
    const int lane = tid & 31;
    const int warp = tid >> 5;
    const int ar   = lane >> 2;
    const int ac   = lane & 3;
    const int j    = lane >> 3;
    const int l7   = lane & 7;

    const int qt = blockIdx.x, h = blockIdx.y, b = blockIdx.z;
    const int q0 = qt * 128;

    // ---- stage Q (fp16, pre-scaled) : group 1 ----
    const __half* Qg = g_Qh + ((size_t)(b * Tt + q0)) * Dm + h * Dh;
    #pragma unroll
    for (int i = 0; i < 4; i++) {
        int f = tid + i * 256;
        cp16(smQ + (f >> 3) * AT_STRIDE_B + (f & 7) * 16,
             Qg + (size_t)(f >> 3) * Dm + (f & 7) * 8);
    }
    CP_COMMIT();

    auto stage_kv = [&](int kt, int buf) {
        const uint32_t smK = smQ + AQ_BYTES + buf * 2 * AK_BYTES;
        const uint32_t smV = smK + AK_BYTES;
        const __half* Kg = g_Kh + ((size_t)(b * Tt + kt * 64)) * Dm + h * Dh;
        const __half* Vg = g_Vh + ((size_t)(b * Tt + kt * 64)) * Dm + h * Dh;
        #pragma unroll
        for (int i = 0; i < 2; i++) {
            int f = tid + i * 256;
            cp16(smK + (f >> 3) * AT_STRIDE_B + (f & 7) * 16,
                 Kg + (size_t)(f >> 3) * Dm + (f & 7) * 8);
            cp16(smV + (f >> 3) * AT_STRIDE_B + (f & 7) * 16,
                 Vg + (size_t)(f >> 3) * Dm + (f & 7) * 8);
        }
    };

    float accO[8][4];
    #pragma unroll
    for (int nt = 0; nt < 8; nt++)
        #pragma unroll
        for (int i = 0; i < 4; i++) accO[nt][i] = 0.f;

    float mrow0 = -1e30f, mrow1 = -1e30f, lrow0 = 0.f, lrow1 = 0.f;
    const int ntiles = 2 * qt + 2;

    stage_kv(0, 0);        // group 2
    CP_COMMIT();

    for (int kt = 0; kt < ntiles; kt++) {
        const int buf = kt & 1;
        const uint32_t smK = smQ + AQ_BYTES + buf * 2 * AK_BYTES;
        const uint32_t smV = smK + AK_BYTES;

        __syncthreads();               // all warps done with buf^1 (tile kt-1)
        if (kt + 1 < ntiles) {
            stage_kv(kt + 1, buf ^ 1); // prefetch next tile
            CP_COMMIT();
            CP_WAIT1();                // tile kt (and Q) arrived; kt+1 may be in flight
        } else {
            CP_WAIT0();
        }
        __syncthreads();

        // ---- S = Q K^T (warp: 16 x 64), 4 ksteps of k16 ----
        float s[8][4];
        #pragma unroll
        for (int nt = 0; nt < 8; nt++)
            #pragma unroll
            for (int i = 0; i < 4; i++) s[nt][i] = 0.f;

        #pragma unroll
        for (int ks = 0; ks < 4; ks++) {
            uint32_t qa[4];
            uint32_t aq = smQ + (uint32_t)(warp * 16 + (j & 1) * 8 + l7) * AT_STRIDE_B
                        + (ks * 16 + (j >> 1) * 8) * 2;
            LDMX4(qa[0], qa[1], qa[2], qa[3], aq);
            #pragma unroll
            for (int pr = 0; pr < 4; pr++) {
                uint32_t b0, b1, b2, b3;
                uint32_t akd = smK + (uint32_t)(pr * 16 + (j >> 1) * 8 + l7) * AT_STRIDE_B
                             + (ks * 16 + (j & 1) * 8) * 2;
                LDMX4(b0, b1, b2, b3, akd);
                MMA16816(s[2 * pr],     qa, b0, b1);
                MMA16816(s[2 * pr + 1], qa, b2, b3);
            }
        }

        // ---- mask + online softmax (log2 domain) ----
        const int r0 = q0 + warp * 16 + ar;
        if (kt >= 2 * qt) {
            #pragma unroll
            for (int nt = 0; nt < 8; nt++) {
                const int c0 = kt * 64 + nt * 8 + 2 * ac;
                if (c0     > r0    ) s[nt][0] = -1e30f;
                if (c0 + 1 > r0    ) s[nt][1] = -1e30f;
                if (c0     > r0 + 8) s[nt][2] = -1e30f;
                if (c0 + 1 > r0 + 8) s[nt][3] = -1e30f;
            }
        }
        float mx0 = -1e30f, mx1 = -1e30f;
        #pragma unroll
        for (int nt = 0; nt < 8; nt++) {
            mx0 = fmaxf(mx0, fmaxf(s[nt][0], s[nt][1]));
            mx1 = fmaxf(mx1, fmaxf(s[nt][2], s[nt][3]));
        }
        mx0 = fmaxf(mx0, __shfl_xor_sync(0xffffffff, mx0, 1));
        mx0 = fmaxf(mx0, __shfl_xor_sync(0xffffffff, mx0, 2));
        mx1 = fmaxf(mx1, __shfl_xor_sync(0xffffffff, mx1, 1));
        mx1 = fmaxf(mx1, __shfl_xor_sync(0xffffffff, mx1, 2));

        const float mn0 = fmaxf(mrow0, mx0);
        const float mn1 = fmaxf(mrow1, mx1);
        const float corr0 = ex2f(mrow0 - mn0);
        const float corr1 = ex2f(mrow1 - mn1);
        mrow0 = mn0; mrow1 = mn1;

        uint32_t ph[8][2];
        float ls0 = 0.f, ls1 = 0.f;
        #pragma unroll
        for (int nt = 0; nt < 8; nt++) {
            float p00 = ex2f(s[nt][0] - mn0);
            float p01 = ex2f(s[nt][1] - mn0);
            float p10 = ex2f(s[nt][2] - mn1);
            float p11 = ex2f(s[nt][3] - mn1);
            ls0 += p00 + p01;
            ls1 += p10 + p11;
            ph[nt][0] = pack_h2(p00, p01);
            ph[nt][1] = pack_h2(p10, p11);
        }
        ls0 += __shfl_xor_sync(0xffffffff, ls0, 1);
        ls0 += __shfl_xor_sync(0xffffffff, ls0, 2);
        ls1 += __shfl_xor_sync(0xffffffff, ls1, 1);
        ls1 += __shfl_xor_sync(0xffffffff, ls1, 2);
        lrow0 = lrow0 * corr0 + ls0;
        lrow1 = lrow1 * corr1 + ls1;

        #pragma unroll
        for (int nt = 0; nt < 8; nt++) {
            accO[nt][0] *= corr0; accO[nt][1] *= corr0;
            accO[nt][2] *= corr1; accO[nt][3] *= corr1;
        }

        // ---- O += P V : P in registers, V via ldmatrix.trans ----
        #pragma unroll
        for (int jk = 0; jk < 4; jk++) {
            uint32_t pa[4] = { ph[2 * jk][0], ph[2 * jk][1], ph[2 * jk + 1][0], ph[2 * jk + 1][1] };
            #pragma unroll
            for (int pr = 0; pr < 4; pr++) {
                uint32_t v0, v1, v2, v3;
                uint32_t av = smV + (uint32_t)(jk * 16 + (j & 1) * 8 + l7) * AT_STRIDE_B
                            + (pr * 16 + (j >> 1) * 8) * 2;
                LDMX4T(v0, v1, v2, v3, av);
                MMA16816(accO[2 * pr],     pa, v0, v1);
                MMA16816(accO[2 * pr + 1], pa, v2, v3);
            }
        }
    }

    // ---- normalize + store ctx as fp16 ----
    const float inv0 = 1.f / lrow0;
    const float inv1 = 1.f / lrow1;
    const int r0 = q0 + warp * 16 + ar;
    __half* og = g_ctxh + ((size_t)(b * Tt)) * Dm + h * Dh;
    #pragma unroll
    for (int nt = 0; nt < 8; nt++) {
        const int col = nt * 8 + 2 * ac;
        *(uint32_t*)&og[(size_t)r0 * Dm + col] =
            pack_h2(accO[nt][0] * inv0, accO[nt][1] * inv0);
        *(uint32_t*)&og[(size_t)(r0 + 8) * Dm + col] =
            pack_h2(accO[nt][2] * inv1, accO[nt][3] * inv1);
    }
}

// ======================= launch =======================
extern "C" void kernel_launch(void* const* d_in, const int* in_sizes, int n_in,
                              void* d_out, int out_size)
{
    const float* x  = (const float*)d_in[0];
    const float* Wq = (const float*)d_in[1];
    const float* Wk = (const float*)d_in[2];
    const float* Wv = (const float*)d_in[3];
    const float* Wo = (const float*)d_in[4];
    float* out = (float*)d_out;

    cudaFuncSetAttribute(gemm_qkv, cudaFuncAttributeMaxDynamicSharedMemorySize, GEMM_SMEM_BYTES);
    cudaFuncSetAttribute(gemm_out, cudaFuncAttributeMaxDynamicSharedMemorySize, GEMM_SMEM_BYTES);
    cudaFuncSetAttribute(attn_mma, cudaFuncAttributeMaxDynamicSharedMemorySize, ATTN_SMEM_BYTES);

    prep_w<<<dim3((Dm * Dm / 4) / 256, 1, 4), 256>>>(Wq, Wk, Wv, Wo);
    prep_x<<<(Mrows * Dm / 4) / 256, 256>>>(x);

    gemm_qkv<<<dim3(Dm / 128, Mrows / 128, 3), 128, GEMM_SMEM_BYTES>>>();

    attn_mma<<<dim3(Tt / 128, Hh, Bz), 256, ATTN_SMEM_BYTES>>>();

    gemm_out<<<dim3(Dm / 128, Mrows / 128, 1), 128, GEMM_SMEM_BYTES>>>(out);
}